// round 8
// baseline (speedup 1.0000x reference)
#include <cuda_runtime.h>
#include <cuda_fp16.h>
#include <math.h>
#include <stdint.h>

#define S_SP 131072      // 32*64*64
#define C_IN 320
#define C_MID 160
#define NB 2
#define TN 128           // spatial tile per CTA
#define NT (S_SP / TN)   // 1024 tiles per (n,t)
#define NPT (NT * 2)     // stat partials per channel (2 warp-halves per tile)
#define KC 32
#define NCH (C_IN / KC)  // 10

// ---------------- scratch ----------------
__device__ __half d_y[(size_t)2 * NB * C_MID * S_SP];  // pre-norm conv outputs (fp16, 168MB)
__device__ float d_psum[2 * NB * C_MID * NPT];
__device__ float d_psq [2 * NB * C_MID * NPT];
__device__ float d_mean[2 * NB * C_MID];
__device__ float d_rstd[2 * NB * C_MID];

// smem layout (words): A[160][36 pad] then B[32][136 pad], double buffered
// SA=36: A-load bank = lq*4+tig  (perfect permutation, conflict-free)
// SB=136 (==8 mod 32): B-load bank = tig*8+lq (perfect permutation, conflict-free)
#define SA 36
#define SB 136
#define A_WORDS (C_MID * SA)              // 5760
#define B_WORDS (KC * SB)                 // 4352
#define STG_WORDS (A_WORDS + B_WORDS)     // 10112
#define SMEM_BYTES (2 * STG_WORDS * 4)    // 80896

// ---------------- helpers ----------------
__device__ __forceinline__ uint32_t smem_u32(const void* p) {
    uint32_t a;
    asm("{ .reg .u64 t; cvta.to.shared.u64 t, %1; cvt.u32.u64 %0, t; }" : "=r"(a) : "l"(p));
    return a;
}
#define CP_ASYNC16(dst, src) asm volatile("cp.async.cg.shared.global [%0], [%1], 16;" :: "r"(dst), "l"(src))
#define CP_COMMIT() asm volatile("cp.async.commit_group;" ::: "memory")
#define CP_WAIT0()  asm volatile("cp.async.wait_group 0;" ::: "memory")

// HMMA.TF32 ignores the low 13 mantissa bits: raw fp32 bit patterns are valid
// tf32 operands (truncation). No cvt needed.
#define MMA(c, a, b) asm volatile( \
    "mma.sync.aligned.m16n8k8.row.col.f32.tf32.tf32.f32 " \
    "{%0,%1,%2,%3}, {%4,%5,%6,%7}, {%8,%9}, {%0,%1,%2,%3};" \
    : "+f"((c)[0]), "+f"((c)[1]), "+f"((c)[2]), "+f"((c)[3]) \
    : "r"((a)[0]), "r"((a)[1]), "r"((a)[2]), "r"((a)[3]), "r"((b)[0]), "r"((b)[1]))

__device__ __forceinline__ float elu1(float v) { return v > 0.0f ? v : expm1f(v); }

// ======================= pass 1: tf32 mma.sync GEMM + per-tile stats =======================
// grid (1024, n=2, t=2), 320 threads (10 warps: 5 M x 2 N), warp tile 32ch x 64sp.
// Bias omitted: it cancels exactly inside instance-norm.
__global__ void __launch_bounds__(320, 2)
gemm_mma_kernel(const float* __restrict__ g, const float* __restrict__ x,
                const float* __restrict__ Wg, const float* __restrict__ Wx) {
    extern __shared__ float sm[];
    const uint32_t smb = smem_u32(sm);
    const int tid = threadIdx.x;
    const int wid = tid >> 5, lane = tid & 31;
    const int tile = blockIdx.x, n = blockIdx.y, t = blockIdx.z;
    const int s0 = tile * TN;

    const float* W   = t ? Wx : Wg;                                   // [160][320]
    const float* inb = (t ? x : g) + (size_t)n * C_IN * S_SP + s0;    // [320][S]

    const int wm = wid >> 1, wn = wid & 1;
    const int lq = lane >> 2, tig = lane & 3;

    float acc[2][8][4];
#pragma unroll
    for (int m = 0; m < 2; m++)
#pragma unroll
        for (int nf = 0; nf < 8; nf++)
#pragma unroll
            for (int j = 0; j < 4; j++) acc[m][nf][j] = 0.0f;

    // ---- staging (cp.async) ----
    auto stage = [&](int k0, int st) {
        const uint32_t ab = smb + (uint32_t)(st * STG_WORDS) * 4u;
        const uint32_t bb = ab + A_WORDS * 4u;
        // W chunk: 160 rows x 32 k -> smem [ch][k], 1280 float4
#pragma unroll 2
        for (int i = tid; i < 1280; i += 320) {
            int row = i >> 3, q = i & 7;
            CP_ASYNC16(ab + (uint32_t)(row * SA + q * 4) * 4u,
                       (const void*)(W + row * C_IN + k0 + q * 4));
        }
        // input chunk: 32 k-rows x 128 sp -> smem [k][sp], 1024 float4
#pragma unroll 2
        for (int i = tid; i < 1024; i += 320) {
            int k = i >> 5, p = i & 31;
            CP_ASYNC16(bb + (uint32_t)(k * SB + p * 4) * 4u,
                       (const void*)(inb + (size_t)(k0 + k) * S_SP + p * 4));
        }
    };

    stage(0, 0); CP_COMMIT();
    CP_WAIT0();
    __syncthreads();

    for (int c = 0; c < NCH; c++) {
        if (c + 1 < NCH) { stage((c + 1) * KC, (c + 1) & 1); CP_COMMIT(); }

        const float* sa = sm + (c & 1) * STG_WORDS;
        const float* sb = sa + A_WORDS;

#pragma unroll
        for (int ks = 0; ks < 4; ks++) {
            const int kk = ks * 8;
            uint32_t a[2][4];
#pragma unroll
            for (int m = 0; m < 2; m++) {
                int r0 = wm * 32 + m * 16 + lq;
                a[m][0] = __float_as_uint(sa[r0 * SA + kk + tig]);
                a[m][1] = __float_as_uint(sa[(r0 + 8) * SA + kk + tig]);
                a[m][2] = __float_as_uint(sa[r0 * SA + kk + tig + 4]);
                a[m][3] = __float_as_uint(sa[(r0 + 8) * SA + kk + tig + 4]);
            }
#pragma unroll
            for (int nf = 0; nf < 8; nf++) {
                int col = wn * 64 + nf * 8 + lq;
                uint32_t b[2];
                b[0] = __float_as_uint(sb[(kk + tig) * SB + col]);
                b[1] = __float_as_uint(sb[(kk + 4 + tig) * SB + col]);
                MMA(acc[0][nf], a[0], b);
                MMA(acc[1][nf], a[1], b);
            }
        }

        if (c + 1 < NCH) CP_WAIT0();
        __syncthreads();
    }

    // ---- epilogue: store y as fp16 (half2) + per-row partial fp32 stats ----
    float rsum[4] = {0.f, 0.f, 0.f, 0.f};
    float rsq [4] = {0.f, 0.f, 0.f, 0.f};
#pragma unroll
    for (int m = 0; m < 2; m++) {
        const int r0 = wm * 32 + m * 16 + lq;
        const size_t base = (size_t)((t * NB + n) * C_MID) * S_SP + s0 + wn * 64 + 2 * tig;
        __half* y0 = d_y + base + (size_t)r0 * S_SP;
        __half* y1 = d_y + base + (size_t)(r0 + 8) * S_SP;
#pragma unroll
        for (int nf = 0; nf < 8; nf++) {
            float v0 = acc[m][nf][0], v1 = acc[m][nf][1];
            float v2 = acc[m][nf][2], v3 = acc[m][nf][3];
            *(__half2*)(y0 + nf * 8) = __floats2half2_rn(v0, v1);
            *(__half2*)(y1 + nf * 8) = __floats2half2_rn(v2, v3);
            rsum[2 * m]     += v0 + v1;
            rsq [2 * m]     += v0 * v0 + v1 * v1;
            rsum[2 * m + 1] += v2 + v3;
            rsq [2 * m + 1] += v2 * v2 + v3 * v3;
        }
    }
#pragma unroll
    for (int j = 0; j < 4; j++) {
        rsum[j] += __shfl_xor_sync(0xffffffffu, rsum[j], 1);
        rsum[j] += __shfl_xor_sync(0xffffffffu, rsum[j], 2);
        rsq [j] += __shfl_xor_sync(0xffffffffu, rsq [j], 1);
        rsq [j] += __shfl_xor_sync(0xffffffffu, rsq [j], 2);
    }
    if (tig == 0) {
#pragma unroll
        for (int j = 0; j < 4; j++) {
            int ch = wm * 32 + (j >> 1) * 16 + (j & 1) * 8 + lq;
            int idx = ((t * NB + n) * C_MID + ch) * NPT + tile * 2 + wn;
            d_psum[idx] = rsum[j];
            d_psq [idx] = rsq [j];
        }
    }
}

// ======================= pass 2: finalize mean / rstd =======================
__global__ void finalize_stats_kernel() {
    const int c = blockIdx.x, n = blockIdx.y, t = blockIdx.z;
    const int base = ((t * NB + n) * C_MID + c) * NPT;
    __shared__ float s1[256], s2[256];
    float a = 0.f, b = 0.f;
    for (int i = threadIdx.x; i < NPT; i += 256) { a += d_psum[base + i]; b += d_psq[base + i]; }
    s1[threadIdx.x] = a; s2[threadIdx.x] = b;
    __syncthreads();
    for (int st = 128; st; st >>= 1) {
        if (threadIdx.x < st) { s1[threadIdx.x] += s1[threadIdx.x + st]; s2[threadIdx.x] += s2[threadIdx.x + st]; }
        __syncthreads();
    }
    if (threadIdx.x == 0) {
        const float inv = 1.0f / (float)S_SP;
        float mean = s1[0] * inv;
        float var  = s2[0] * inv - mean * mean;
        d_mean[(t * NB + n) * C_MID + c] = mean;
        d_rstd[(t * NB + n) * C_MID + c] = rsqrtf(var + 1e-5f);
    }
}

// ======================= pass 3: norm + elu + psi + multiply =======================
// grid (S_SP/512, n=2), 256 threads, 2 spatial/thread (half2 y loads, float2 x).
__global__ void __launch_bounds__(256)
psi_mul_kernel(const float* __restrict__ x, const float* __restrict__ Wpsi,
               const float* __restrict__ bpsi, float* __restrict__ out) {
    const int n = blockIdx.y;
    const int s = (blockIdx.x * 256 + threadIdx.x) * 2;

    __shared__ float sWp[C_MID], sMg[C_MID], sRg[C_MID], sMx[C_MID], sRx[C_MID];
    if (threadIdx.x < C_MID) {
        int c = threadIdx.x;
        sWp[c] = Wpsi[c];
        sMg[c] = d_mean[(0 * NB + n) * C_MID + c];
        sRg[c] = d_rstd[(0 * NB + n) * C_MID + c];
        sMx[c] = d_mean[(1 * NB + n) * C_MID + c];
        sRx[c] = d_rstd[(1 * NB + n) * C_MID + c];
    }
    __syncthreads();

    const float b0 = bpsi[0];
    float z0 = b0, z1 = b0;
    const __half* yg = d_y + ((size_t)(0 * NB + n) * C_MID) * S_SP + s;
    const __half* yx = d_y + ((size_t)(1 * NB + n) * C_MID) * S_SP + s;
#pragma unroll 8
    for (int c = 0; c < C_MID; c++) {
        float2 vg = __half22float2(*(const __half2*)(yg + (size_t)c * S_SP));
        float2 vx = __half22float2(*(const __half2*)(yx + (size_t)c * S_SP));
        float mg = sMg[c], rg = sRg[c], mx = sMx[c], rx = sRx[c], wp = sWp[c];
        z0 = fmaf(wp, elu1((vg.x - mg) * rg) + elu1((vx.x - mx) * rx), z0);
        z1 = fmaf(wp, elu1((vg.y - mg) * rg) + elu1((vx.y - mx) * rx), z1);
    }
    const float p0 = 1.0f / (1.0f + expf(-z0));
    const float p1 = 1.0f / (1.0f + expf(-z1));

    const float* xin = x   + ((size_t)n * C_IN) * S_SP + s;
    float*       ob  = out + ((size_t)n * C_IN) * S_SP + s;
#pragma unroll 8
    for (int c = 0; c < C_IN; c++) {
        float2 xv = *(const float2*)(xin + (size_t)c * S_SP);
        xv.x *= p0; xv.y *= p1;
        *(float2*)(ob + (size_t)c * S_SP) = xv;
    }
}

// ======================= launch =======================
extern "C" void kernel_launch(void* const* d_in, const int* in_sizes, int n_in,
                              void* d_out, int out_size) {
    const float* g    = (const float*)d_in[0];
    const float* x    = (const float*)d_in[1];
    const float* Wg   = (const float*)d_in[2];
    const float* Wx   = (const float*)d_in[4];
    const float* Wpsi = (const float*)d_in[6];
    const float* bpsi = (const float*)d_in[7];
    float* out = (float*)d_out;

    cudaFuncSetAttribute(gemm_mma_kernel, cudaFuncAttributeMaxDynamicSharedMemorySize, SMEM_BYTES);

    gemm_mma_kernel<<<dim3(NT, NB, 2), 320, SMEM_BYTES>>>(g, x, Wg, Wx);
    finalize_stats_kernel<<<dim3(C_MID, NB, 2), 256>>>();
    psi_mul_kernel<<<dim3(S_SP / 512, NB), 256>>>(x, Wpsi, bpsi, out);
}